// round 1
// baseline (speedup 1.0000x reference)
#include <cuda_runtime.h>

// LightCSCF: bpr + reg + cscf losses.
// Key identity: total = e1@e2^T + e1@e1^T = e1 @ (e1+e2)^T  -> single 8192x8192x64 GEMM,
// fused epilogue g(x) = exp(x/T) + max(1, exp(x/T)*exp(-margin/T)), fused row-sum.

#define BATCH 8192
#define DIM   64
#define NCB   64        // number of 128-wide column blocks (8192/128)
#define PAD   132       // smem row pitch in floats (k-major tiles), 132%32=4 -> <=4-way store conflict, 16B aligned reads

__device__ float g_e1[BATCH * DIM];       // normalized user embeddings
__device__ float g_f [BATCH * DIM];       // e1 + e2
__device__ float g_pos[BATCH];            // cscf pos_score per row
__device__ float g_bpr[BATCH];            // log_sigmoid(pos-neg) per row
__device__ float g_sq [BATCH];            // sum-of-squares per row (u^2+p^2+n^2)
__device__ float g_partial[BATCH * NCB];  // row-sum partials per column block
__device__ float g_blk[NCB * 3];          // per-block (loss, bpr, sq) sums from rowloss kernel

// ---------------------------------------------------------------------------
// Kernel 1: gather + per-row stats + normalized vectors. One warp per row.
// ---------------------------------------------------------------------------
__global__ void __launch_bounds__(256) prep_kernel(
    const float* __restrict__ ut, const float* __restrict__ it,
    const int* __restrict__ user, const int* __restrict__ pos,
    const int* __restrict__ neg)
{
    int row  = blockIdx.x * 8 + (threadIdx.x >> 5);
    int lane = threadIdx.x & 31;

    const float2* up  = (const float2*)(ut + (long long)user[row] * DIM);
    const float2* pp  = (const float2*)(it + (long long)pos[row]  * DIM);
    const float2* npp = (const float2*)(it + (long long)neg[row]  * DIM);
    float2 u = up[lane], p = pp[lane], n = npp[lane];

    float s_up = u.x * p.x + u.y * p.y;
    float s_un = u.x * n.x + u.y * n.y;
    float s_uu = u.x * u.x + u.y * u.y;
    float s_pp = p.x * p.x + p.y * p.y;
    float s_nn = n.x * n.x + n.y * n.y;

    #pragma unroll
    for (int off = 16; off; off >>= 1) {
        s_up += __shfl_xor_sync(0xffffffffu, s_up, off);
        s_un += __shfl_xor_sync(0xffffffffu, s_un, off);
        s_uu += __shfl_xor_sync(0xffffffffu, s_uu, off);
        s_pp += __shfl_xor_sync(0xffffffffu, s_pp, off);
        s_nn += __shfl_xor_sync(0xffffffffu, s_nn, off);
    }

    float inu = 1.0f / fmaxf(sqrtf(s_uu), 1e-12f);
    float inp = 1.0f / fmaxf(sqrtf(s_pp), 1e-12f);

    float2 e1; e1.x = u.x * inu; e1.y = u.y * inu;
    float2 e2; e2.x = p.x * inp; e2.y = p.y * inp;
    ((float2*)(g_e1 + row * DIM))[lane] = e1;
    float2 f; f.x = e1.x + e2.x; f.y = e1.y + e2.y;
    ((float2*)(g_f + row * DIM))[lane] = f;

    if (lane == 0) {
        // cscf positive score: sim = (u.p)/(|u||p|); T=0.2, margin=0.8 -> C=exp(-4)
        float sim = s_up * inu * inp;
        float t = __expf(sim * 5.0f);
        g_pos[row] = t + fmaxf(1.0f, t * 0.0183156393f);
        // bpr: log_sigmoid(pos - neg), numerically stable
        float x = s_up - s_un;
        g_bpr[row] = fminf(x, 0.0f) - log1pf(__expf(-fabsf(x)));
        g_sq[row] = s_uu + s_pp + s_nn;
    }
}

// ---------------------------------------------------------------------------
// Kernel 2: fused GEMM total = e1 @ f^T with epilogue + row-sum.
// 128x128 tile per CTA, 256 threads, 8x8 per thread, K split in two 32-halves
// so static smem stays under 48KB (2 * 32*132*4 = 33792B).
// ---------------------------------------------------------------------------
__global__ void __launch_bounds__(256) gemm_kernel()
{
    __shared__ __align__(16) float a_s[32 * PAD];
    __shared__ __align__(16) float b_s[32 * PAD];

    int tid = threadIdx.x;
    int tx = tid & 15;
    int ty = tid >> 4;
    int rowBase = blockIdx.y * 128;
    int colBase = blockIdx.x * 128;

    float acc[8][8];
    #pragma unroll
    for (int i = 0; i < 8; i++)
        #pragma unroll
        for (int j = 0; j < 8; j++) acc[i][j] = 0.0f;

    #pragma unroll
    for (int kb = 0; kb < 64; kb += 32) {
        __syncthreads();
        // Load k-major tiles: a_s[k*PAD + r] = e1[rowBase+r][kb+k]
        #pragma unroll
        for (int l = 0; l < 16; l++) {
            int i = tid + l * 256;      // 0..4095
            int r = i >> 5;             // 0..127
            int k = i & 31;             // 0..31  (coalesced global reads)
            a_s[k * PAD + r] = g_e1[(rowBase + r) * DIM + kb + k];
            b_s[k * PAD + r] = g_f [(colBase + r) * DIM + kb + k];
        }
        __syncthreads();

        #pragma unroll 8
        for (int k = 0; k < 32; k++) {
            float4 a0 = *(const float4*)&a_s[k * PAD + ty * 8];
            float4 a1 = *(const float4*)&a_s[k * PAD + ty * 8 + 4];
            float4 b0 = *(const float4*)&b_s[k * PAD + tx * 8];
            float4 b1 = *(const float4*)&b_s[k * PAD + tx * 8 + 4];
            float av[8] = {a0.x, a0.y, a0.z, a0.w, a1.x, a1.y, a1.z, a1.w};
            float bv[8] = {b0.x, b0.y, b0.z, b0.w, b1.x, b1.y, b1.z, b1.w};
            #pragma unroll
            for (int i = 0; i < 8; i++)
                #pragma unroll
                for (int j = 0; j < 8; j++)
                    acc[i][j] = fmaf(av[i], bv[j], acc[i][j]);
        }
    }

    // Epilogue: g(x) = t + max(1, t*C), t = exp(x/T); reduce over the 128 cols.
    #pragma unroll
    for (int i = 0; i < 8; i++) {
        float rs = 0.0f;
        #pragma unroll
        for (int j = 0; j < 8; j++) {
            float t = __expf(acc[i][j] * 5.0f);
            rs += t + fmaxf(1.0f, t * 0.0183156393f);
        }
        // reduce across the 16 threads sharing this row (width-16 segments)
        #pragma unroll
        for (int off = 8; off; off >>= 1)
            rs += __shfl_down_sync(0xffffffffu, rs, off, 16);
        if (tx == 0)
            g_partial[(rowBase + ty * 8 + i) * NCB + blockIdx.x] = rs;
    }
}

// ---------------------------------------------------------------------------
// Kernel 3: per-row loss + per-block partial sums (deterministic, no atomics).
// ---------------------------------------------------------------------------
__global__ void __launch_bounds__(128) rowloss_kernel()
{
    int tid = threadIdx.x;
    int row = blockIdx.x * 128 + tid;

    const float4* pp = (const float4*)(g_partial + row * NCB);
    float rs = 0.0f;
    #pragma unroll
    for (int i = 0; i < NCB / 4; i++) {
        float4 v = pp[i];
        rs += v.x + v.y + v.z + v.w;
    }
    float loss = -logf(g_pos[row] / rs + 1e-5f);
    float bpr = g_bpr[row];
    float sq  = g_sq[row];

    __shared__ float sl[128], sb[128], ss[128];
    sl[tid] = loss; sb[tid] = bpr; ss[tid] = sq;
    __syncthreads();
    #pragma unroll
    for (int s = 64; s; s >>= 1) {
        if (tid < s) {
            sl[tid] += sl[tid + s];
            sb[tid] += sb[tid + s];
            ss[tid] += ss[tid + s];
        }
        __syncthreads();
    }
    if (tid == 0) {
        g_blk[blockIdx.x * 3 + 0] = sl[0];
        g_blk[blockIdx.x * 3 + 1] = sb[0];
        g_blk[blockIdx.x * 3 + 2] = ss[0];
    }
}

// ---------------------------------------------------------------------------
// Kernel 4: final reduction -> (bpr, reg, na)
// ---------------------------------------------------------------------------
__global__ void final_kernel(float* __restrict__ out)
{
    int t = threadIdx.x;  // 32 threads
    float l = 0.0f, b = 0.0f, s = 0.0f;
    for (int i = t; i < NCB; i += 32) {
        l += g_blk[i * 3 + 0];
        b += g_blk[i * 3 + 1];
        s += g_blk[i * 3 + 2];
    }
    #pragma unroll
    for (int off = 16; off; off >>= 1) {
        l += __shfl_xor_sync(0xffffffffu, l, off);
        b += __shfl_xor_sync(0xffffffffu, b, off);
        s += __shfl_xor_sync(0xffffffffu, s, off);
    }
    if (t == 0) {
        out[0] = -b / (float)BATCH;                  // bpr
        out[1] = 1e-4f * 0.5f * s / (float)BATCH;    // reg
        out[2] = 0.5f * l / (float)BATCH;            // na (LAMBDA_GAMMA * mean)
    }
}

extern "C" void kernel_launch(void* const* d_in, const int* in_sizes, int n_in,
                              void* d_out, int out_size)
{
    const float* ut  = (const float*)d_in[0];
    const float* it  = (const float*)d_in[1];
    const int* user  = (const int*)d_in[2];
    const int* pos   = (const int*)d_in[3];
    const int* neg   = (const int*)d_in[4];

    prep_kernel<<<BATCH / 8, 256>>>(ut, it, user, pos, neg);
    dim3 grid(NCB, NCB);
    gemm_kernel<<<grid, 256>>>();
    rowloss_kernel<<<NCB, 128>>>();
    final_kernel<<<1, 32>>>((float*)d_out);
}